// round 1
// baseline (speedup 1.0000x reference)
#include <cuda_runtime.h>
#include <cuda_bf16.h>
#include <math.h>

// ---------------- constants ----------------
#define BATCH 32
#define LSEQ  196          // 14*14 patches
#define MROWS (BATCH*LSEQ) // 6272
#define DMODEL 512
#define DINNER 256
#define DSTATE 16
#define DTRANK 16
#define NHEAD 8
#define HDIM 64
#define KPATCH 768         // 3*16*16

// ---------------- scratch (device globals; allocation-free) ----------------
__device__ float g_acol[MROWS*KPATCH];   // im2col patches
__device__ float g_t   [MROWS*DMODEL];   // running residual stream
__device__ float g_h   [MROWS*DMODEL];   // layernorm output (reused)
__device__ float g_xz  [MROWS*DMODEL];   // in_proj output [xm | z]
__device__ float g_xmz [MROWS*DMODEL];   // silu(dwconv()) of [xm | z]
__device__ float g_dt  [MROWS*DINNER];
__device__ float g_Bm  [MROWS*DSTATE];
__device__ float g_Cm  [MROWS*DSTATE];
__device__ float g_ycat[MROWS*DMODEL];   // [y+xm*Dp | z]
__device__ float g_qkv [MROWS*3*DMODEL];
__device__ float g_o   [MROWS*DMODEL];
__device__ float g_mid [MROWS*4*DMODEL];
__device__ float g_tbar[BATCH*DMODEL];

// ---------------- im2col ----------------
__global__ void im2col_k(const float* __restrict__ x) {
    int idx = blockIdx.x * blockDim.x + threadIdx.x;
    if (idx >= MROWS*KPATCH) return;
    int k = idx % KPATCH;
    int m = idx / KPATCH;
    int b = m / LSEQ, l = m % LSEQ;
    int ph = l / 14, pw = l % 14;
    int c = k / 256, rem = k % 256;
    int i = rem / 16, j = rem % 16;
    g_acol[idx] = x[(((size_t)b*3 + c)*224 + (ph*16 + i))*224 + (pw*16 + j)];
}

// ---------------- tiled SGEMM:  C[M,N] = A[M,K] @ W[N,K]^T (+bias)(+act)(+res) ----------------
#define ACT_NONE 0
#define ACT_GELU 1

template<int ACT, bool BIAS, bool RES>
__global__ void __launch_bounds__(256)
gemm_k(const float* __restrict__ A, const float* __restrict__ W,
       const float* __restrict__ bias, float* __restrict__ C,
       int N, int K) {
    __shared__ float As[16][68];
    __shared__ float Bs[16][68];
    int tid = threadIdx.x;
    int tx = tid & 15, ty = tid >> 4;
    int m0 = blockIdx.y * 64, n0 = blockIdx.x * 64;
    int lr = tid >> 2;            // 0..63
    int lc = (tid & 3) << 2;      // 0,4,8,12
    const float* Ap = A + (size_t)(m0 + lr) * K + lc;
    const float* Wp = W + (size_t)(n0 + lr) * K + lc;
    float acc[4][4] = {};
    for (int k0 = 0; k0 < K; k0 += 16) {
        float4 av = *(const float4*)(Ap + k0);
        float4 wv = *(const float4*)(Wp + k0);
        As[lc+0][lr] = av.x; As[lc+1][lr] = av.y; As[lc+2][lr] = av.z; As[lc+3][lr] = av.w;
        Bs[lc+0][lr] = wv.x; Bs[lc+1][lr] = wv.y; Bs[lc+2][lr] = wv.z; Bs[lc+3][lr] = wv.w;
        __syncthreads();
#pragma unroll
        for (int kk = 0; kk < 16; kk++) {
            float a[4], b[4];
#pragma unroll
            for (int i = 0; i < 4; i++) a[i] = As[kk][ty*4 + i];
#pragma unroll
            for (int j = 0; j < 4; j++) b[j] = Bs[kk][tx*4 + j];
#pragma unroll
            for (int i = 0; i < 4; i++)
#pragma unroll
                for (int j = 0; j < 4; j++) acc[i][j] += a[i] * b[j];
        }
        __syncthreads();
    }
#pragma unroll
    for (int i = 0; i < 4; i++) {
        int m = m0 + ty*4 + i;
#pragma unroll
        for (int j = 0; j < 4; j++) {
            int n = n0 + tx*4 + j;
            float v = acc[i][j];
            if (BIAS) v += bias[n];
            if (ACT == ACT_GELU) {
                float xx = v;
                v = 0.5f * xx * (1.f + tanhf(0.7978845608028654f * (xx + 0.044715f*xx*xx*xx)));
            }
            if (RES) v += C[(size_t)m*N + n];
            C[(size_t)m*N + n] = v;
        }
    }
}

// ---------------- layernorm (row = 512) ----------------
__global__ void ln_k(const float* __restrict__ in, const float* __restrict__ g,
                     const float* __restrict__ be, float* __restrict__ out) {
    __shared__ float r1[4], r2[4];
    int m = blockIdx.x;
    const float* row = in + (size_t)m * DMODEL;
    float s = 0.f, ss = 0.f;
    for (int i = threadIdx.x; i < DMODEL; i += 128) { float v = row[i]; s += v; ss += v*v; }
#pragma unroll
    for (int off = 16; off; off >>= 1) {
        s  += __shfl_xor_sync(~0u, s, off);
        ss += __shfl_xor_sync(~0u, ss, off);
    }
    int w = threadIdx.x >> 5, lane = threadIdx.x & 31;
    if (lane == 0) { r1[w] = s; r2[w] = ss; }
    __syncthreads();
    s  = r1[0] + r1[1] + r1[2] + r1[3];
    ss = r2[0] + r2[1] + r2[2] + r2[3];
    float mean = s * (1.f/DMODEL);
    float var  = ss * (1.f/DMODEL) - mean*mean;
    float rs   = rsqrtf(var + 1e-6f);
    for (int i = threadIdx.x; i < DMODEL; i += 128)
        out[(size_t)m*DMODEL + i] = (row[i] - mean) * rs * g[i] + be[i];
}

// ---------------- causal depthwise conv (width 4) + SiLU, both halves ----------------
__global__ void dwconv_silu_k(const float* __restrict__ cxw, const float* __restrict__ cxb,
                              const float* __restrict__ czw, const float* __restrict__ czb) {
    int idx = blockIdx.x * blockDim.x + threadIdx.x;  // over MROWS*DMODEL
    if (idx >= MROWS*DMODEL) return;
    int c = idx % DMODEL;
    int m = idx / DMODEL;
    int l = m % LSEQ;
    const float* w; float acc;
    if (c < DINNER) { w = cxw + c*4;          acc = cxb[c]; }
    else            { w = czw + (c-DINNER)*4; acc = czb[c-DINNER]; }
#pragma unroll
    for (int k = 0; k < 4; k++) {
        int lp = l - 3 + k;
        if (lp >= 0) acc += w[k] * g_xz[(size_t)(m - 3 + k)*DMODEL + c];
    }
    g_xmz[idx] = acc / (1.f + __expf(-acc));
}

// ---------------- x_proj (48 outs) + dt_proj + softplus ----------------
__global__ void xproj_dt_k(const float* __restrict__ xpw, const float* __restrict__ dtw,
                           const float* __restrict__ dtb) {
    int m = blockIdx.x;
    __shared__ float xs[DINNER];
    __shared__ float dtr[DTRANK];
    int tid = threadIdx.x;                      // 256
    xs[tid] = g_xmz[(size_t)m*DMODEL + tid];    // xm half
    __syncthreads();
    int w = tid >> 5, lane = tid & 31;
    for (int j = w; j < DTRANK + 2*DSTATE; j += 8) {
        const float* wr = xpw + j*DINNER;
        float p = 0.f;
        for (int e = lane; e < DINNER; e += 32) p += xs[e] * wr[e];
#pragma unroll
        for (int off = 16; off; off >>= 1) p += __shfl_xor_sync(~0u, p, off);
        if (lane == 0) {
            if (j < DTRANK)              dtr[j] = p;
            else if (j < DTRANK+DSTATE)  g_Bm[(size_t)m*DSTATE + (j-DTRANK)] = p;
            else                         g_Cm[(size_t)m*DSTATE + (j-DTRANK-DSTATE)] = p;
        }
    }
    __syncthreads();
    float s = dtb[tid];
#pragma unroll
    for (int r = 0; r < DTRANK; r++) s += dtr[r] * dtw[tid*DTRANK + r];
    g_dt[(size_t)m*DINNER + tid] = (s > 20.f) ? s : log1pf(__expf(s));
}

// ---------------- selective scan (block = batch, thread = channel) ----------------
__global__ void scan_k(const float* __restrict__ A_log, const float* __restrict__ Dp) {
    int b = blockIdx.x;
    int d = threadIdx.x;     // 256
    __shared__ float Bs[DSTATE], Cs[DSTATE];
    float Arow[DSTATE];
#pragma unroll
    for (int n = 0; n < DSTATE; n++) Arow[n] = -__expf(A_log[d*DSTATE + n]);
    float hst[DSTATE] = {};
    float Dv = Dp[d];
    for (int l = 0; l < LSEQ; l++) {
        size_t m = (size_t)b*LSEQ + l;
        __syncthreads();
        if (d < DSTATE)        Bs[d] = g_Bm[m*DSTATE + d];
        else if (d < 2*DSTATE) Cs[d - DSTATE] = g_Cm[m*DSTATE + (d - DSTATE)];
        __syncthreads();
        float dt = g_dt[m*DINNER + d];
        float u  = g_xmz[m*DMODEL + d];
        float du = dt * u;
        float acc = 0.f;
#pragma unroll
        for (int n = 0; n < DSTATE; n++) {
            float dA = __expf(dt * Arow[n]);
            hst[n] = dA * hst[n] + du * Bs[n];
            acc += hst[n] * Cs[n];
        }
        g_ycat[m*DMODEL + d]          = acc + u * Dv;
        g_ycat[m*DMODEL + DINNER + d] = g_xmz[m*DMODEL + DINNER + d];
    }
}

// ---------------- attention: block per (b, head), K/V staged in smem ----------------
__global__ void attn_k() {
    extern __shared__ float sm[];
    float* Ks = sm;                       // [196][65]
    float* Vs = Ks + LSEQ*65;             // [196][65]
    float* Qs = Vs + LSEQ*65;             // [8][64]
    float* Aw = Qs + 8*64;                // [8][196]
    int b = blockIdx.x >> 3, h = blockIdx.x & 7;
    int tid = threadIdx.x;                // 256
    const float* base = g_qkv + (size_t)b * LSEQ * (3*DMODEL);
    for (int i = tid; i < LSEQ*HDIM; i += 256) {
        int l = i / HDIM, d = i % HDIM;
        Ks[l*65 + d] = base[(size_t)l*(3*DMODEL) + DMODEL   + h*HDIM + d];
        Vs[l*65 + d] = base[(size_t)l*(3*DMODEL) + 2*DMODEL + h*HDIM + d];
    }
    __syncthreads();
    int w = tid >> 5, lane = tid & 31;
    float* qr = Qs + w*HDIM;
    float* aw = Aw + w*LSEQ;
    for (int q = w; q < LSEQ; q += 8) {
        qr[lane]      = base[(size_t)q*(3*DMODEL) + h*HDIM + lane];
        qr[lane + 32] = base[(size_t)q*(3*DMODEL) + h*HDIM + lane + 32];
        __syncwarp();
        float lmax = -1e30f;
        for (int k = lane; k < LSEQ; k += 32) {
            float s = 0.f;
            const float* kr = Ks + k*65;
#pragma unroll 16
            for (int d = 0; d < HDIM; d++) s += qr[d] * kr[d];
            s *= 0.125f;                      // 1/sqrt(64)
            aw[k] = s;
            lmax = fmaxf(lmax, s);
        }
#pragma unroll
        for (int off = 16; off; off >>= 1) lmax = fmaxf(lmax, __shfl_xor_sync(~0u, lmax, off));
        float lsum = 0.f;
        for (int k = lane; k < LSEQ; k += 32) { float e = __expf(aw[k] - lmax); aw[k] = e; lsum += e; }
#pragma unroll
        for (int off = 16; off; off >>= 1) lsum += __shfl_xor_sync(~0u, lsum, off);
        float inv = 1.f / lsum;
        __syncwarp();
        float o0 = 0.f, o1 = 0.f;
        for (int k = 0; k < LSEQ; k++) {
            float a = aw[k];
            o0 += a * Vs[k*65 + lane];
            o1 += a * Vs[k*65 + lane + 32];
        }
        float* orow = g_o + ((size_t)(b*LSEQ + q))*DMODEL + h*HDIM;
        orow[lane]      = o0 * inv;
        orow[lane + 32] = o1 * inv;
        __syncwarp();
    }
}

// ---------------- mean over sequence ----------------
__global__ void meanrow_k() {
    int b = blockIdx.x, d = threadIdx.x;  // 512
    float s = 0.f;
    for (int l = 0; l < LSEQ; l++) s += g_t[((size_t)b*LSEQ + l)*DMODEL + d];
    g_tbar[b*DMODEL + d] = s * (1.f/LSEQ);
}

// ---------------- head (1024) + fc (4), fused per batch ----------------
__global__ void headfc_k(const float* __restrict__ hw, const float* __restrict__ hb,
                         const float* __restrict__ fw, const float* __restrict__ fb,
                         float* __restrict__ out) {
    int b = blockIdx.x;
    __shared__ float ts[DMODEL];
    __shared__ float ps[1024];
    int tid = threadIdx.x;  // 256
    ts[tid]       = g_tbar[b*DMODEL + tid];
    ts[tid + 256] = g_tbar[b*DMODEL + tid + 256];
    __syncthreads();
    int w = tid >> 5, lane = tid & 31;
    for (int j = w; j < 1024; j += 8) {
        const float* wr = hw + j*DMODEL;
        float p = 0.f;
        for (int e = lane; e < DMODEL; e += 32) p += ts[e] * wr[e];
#pragma unroll
        for (int off = 16; off; off >>= 1) p += __shfl_xor_sync(~0u, p, off);
        if (lane == 0) ps[j] = p + hb[j];
    }
    __syncthreads();
    if (w == 0) {
        for (int c = 0; c < 4; c++) {
            float p = 0.f;
            for (int e = lane; e < 1024; e += 32) p += ps[e] * fw[c*1024 + e];
#pragma unroll
            for (int off = 16; off; off >>= 1) p += __shfl_xor_sync(~0u, p, off);
            if (lane == 0) out[b*4 + c] = p + fb[c];
        }
    }
}

// ---------------- launch ----------------
extern "C" void kernel_launch(void* const* d_in, const int* in_sizes, int n_in,
                              void* d_out, int out_size) {
    const float* x        = (const float*)d_in[0];
    const float* patch_w  = (const float*)d_in[1];
    const float* patch_b  = (const float*)d_in[2];
    const float* ln1_g    = (const float*)d_in[3];
    const float* ln1_b    = (const float*)d_in[4];
    const float* in_proj  = (const float*)d_in[5];
    const float* convx_w  = (const float*)d_in[6];
    const float* convx_b  = (const float*)d_in[7];
    const float* convz_w  = (const float*)d_in[8];
    const float* convz_b  = (const float*)d_in[9];
    const float* x_proj_w = (const float*)d_in[10];
    const float* dt_proj_w= (const float*)d_in[11];
    const float* dt_proj_b= (const float*)d_in[12];
    const float* A_log    = (const float*)d_in[13];
    const float* Dp       = (const float*)d_in[14];
    const float* out_proj = (const float*)d_in[15];
    const float* ln2_g    = (const float*)d_in[16];
    const float* ln2_b    = (const float*)d_in[17];
    const float* qkv_w    = (const float*)d_in[18];
    const float* attn_pw  = (const float*)d_in[19];
    const float* ln3_g    = (const float*)d_in[20];
    const float* ln3_b    = (const float*)d_in[21];
    const float* mlp_w1   = (const float*)d_in[22];
    const float* mlp_b1   = (const float*)d_in[23];
    const float* mlp_w2   = (const float*)d_in[24];
    const float* mlp_b2   = (const float*)d_in[25];
    const float* head_w   = (const float*)d_in[26];
    const float* head_b   = (const float*)d_in[27];
    const float* fc_w     = (const float*)d_in[28];
    const float* fc_b     = (const float*)d_in[29];

    float *acol, *t, *h, *xz, *qkv, *o, *mid, *ycat;
    cudaGetSymbolAddress((void**)&acol, g_acol);
    cudaGetSymbolAddress((void**)&t,    g_t);
    cudaGetSymbolAddress((void**)&h,    g_h);
    cudaGetSymbolAddress((void**)&xz,   g_xz);
    cudaGetSymbolAddress((void**)&qkv,  g_qkv);
    cudaGetSymbolAddress((void**)&o,    g_o);
    cudaGetSymbolAddress((void**)&mid,  g_mid);
    cudaGetSymbolAddress((void**)&ycat, g_ycat);

    const int ATTN_SMEM = (LSEQ*65*2 + 8*64 + 8*LSEQ) * (int)sizeof(float);  // ~110 KB
    cudaFuncSetAttribute(attn_k, cudaFuncAttributeMaxDynamicSharedMemorySize, ATTN_SMEM);

    dim3 g512(DMODEL/64, MROWS/64);     // (8, 98)
    dim3 g1536(3*DMODEL/64, MROWS/64);  // (24, 98)
    dim3 g2048(4*DMODEL/64, MROWS/64);  // (32, 98)

    // 1. patch embed = im2col + GEMM(+bias)
    im2col_k<<<(MROWS*KPATCH + 255)/256, 256>>>(x);
    gemm_k<ACT_NONE, true,  false><<<g512, 256>>>(acol, patch_w, patch_b, t, DMODEL, KPATCH);
    // 2. mamba block
    ln_k<<<MROWS, 128>>>(t, ln1_g, ln1_b, h);
    gemm_k<ACT_NONE, false, false><<<g512, 256>>>(h, in_proj, nullptr, xz, DMODEL, DMODEL);
    dwconv_silu_k<<<(MROWS*DMODEL)/256, 256>>>(convx_w, convx_b, convz_w, convz_b);
    xproj_dt_k<<<MROWS, 256>>>(x_proj_w, dt_proj_w, dt_proj_b);
    scan_k<<<BATCH, 256>>>(A_log, Dp);
    gemm_k<ACT_NONE, false, true ><<<g512, 256>>>(ycat, out_proj, nullptr, t, DMODEL, DMODEL);
    // 3. attention block
    ln_k<<<MROWS, 128>>>(t, ln2_g, ln2_b, h);
    gemm_k<ACT_NONE, false, false><<<g1536, 256>>>(h, qkv_w, nullptr, qkv, 3*DMODEL, DMODEL);
    attn_k<<<BATCH*NHEAD, 256, ATTN_SMEM>>>();
    gemm_k<ACT_NONE, false, true ><<<g512, 256>>>(o, attn_pw, nullptr, t, DMODEL, DMODEL);
    // 4. MLP block
    ln_k<<<MROWS, 128>>>(t, ln3_g, ln3_b, h);
    gemm_k<ACT_GELU, true,  false><<<g2048, 256>>>(h, mlp_w1, mlp_b1, mid, 4*DMODEL, DMODEL);
    gemm_k<ACT_NONE, true,  true ><<<g512, 256>>>(mid, mlp_w2, mlp_b2, t, DMODEL, 4*DMODEL);
    // 5. head: mean-pool first (linearity), then 512->1024->4
    meanrow_k<<<BATCH, DMODEL>>>();
    headfc_k<<<BATCH, 256>>>(head_w, head_b, fc_w, fc_b, (float*)d_out);
}

// round 2
// speedup vs baseline: 1.0665x; 1.0665x over previous
#include <cuda_runtime.h>
#include <cuda_bf16.h>
#include <math.h>
#include <stdint.h>

// ---------------- constants ----------------
#define BATCH 32
#define LSEQ  196
#define MROWS (BATCH*LSEQ) // 6272
#define DMODEL 512
#define DINNER 256
#define DSTATE 16
#define DTRANK 16
#define NHEAD 8
#define HDIM 64
#define KPATCH 768

// ---------------- scratch ----------------
__device__ float g_acol[MROWS*KPATCH];
__device__ float g_t   [MROWS*DMODEL];
__device__ float g_h   [MROWS*DMODEL];
__device__ float g_xz  [MROWS*DMODEL];
__device__ float g_xmz [MROWS*DMODEL];
__device__ float g_dt  [MROWS*DINNER];
__device__ float g_Bm  [MROWS*DSTATE];
__device__ float g_Cm  [MROWS*DSTATE];
__device__ float g_ycat[MROWS*DMODEL];
__device__ float g_qkv [MROWS*3*DMODEL];
__device__ float g_o   [MROWS*DMODEL];
__device__ float g_mid [MROWS*4*DMODEL];
__device__ float g_tbar[BATCH*DMODEL];

// ---------------- im2col ----------------
__global__ void im2col_k(const float* __restrict__ x) {
    int idx = blockIdx.x * blockDim.x + threadIdx.x;
    if (idx >= MROWS*KPATCH) return;
    int k = idx % KPATCH;
    int m = idx / KPATCH;
    int b = m / LSEQ, l = m % LSEQ;
    int ph = l / 14, pw = l % 14;
    int c = k / 256, rem = k % 256;
    int i = rem / 16, j = rem % 16;
    g_acol[idx] = x[(((size_t)b*3 + c)*224 + (ph*16 + i))*224 + (pw*16 + j)];
}

// ---------------- 3xTF32 tensor-core GEMM ----------------
// C[M,N] = A[M,K] @ W[N,K]^T (+bias)(+gelu)(+residual)
#define ACT_NONE 0
#define ACT_GELU 1
#define BM 128
#define BN 128
#define BKG 16

__device__ __forceinline__ void split_tf32(float x, uint32_t& hi, uint32_t& lo) {
    uint32_t h;
    asm("cvt.rna.tf32.f32 %0, %1;" : "=r"(h) : "f"(x));
    float r = x - __uint_as_float(h);
    uint32_t l;
    asm("cvt.rna.tf32.f32 %0, %1;" : "=r"(l) : "f"(r));
    hi = h; lo = l;
}

#define MMA_TF32(d, a0,a1,a2,a3, b0,b1) \
    asm volatile("mma.sync.aligned.m16n8k8.row.col.f32.tf32.tf32.f32 " \
        "{%0,%1,%2,%3},{%4,%5,%6,%7},{%8,%9},{%0,%1,%2,%3};" \
        : "+f"(d[0]),"+f"(d[1]),"+f"(d[2]),"+f"(d[3]) \
        : "r"(a0),"r"(a1),"r"(a2),"r"(a3),"r"(b0),"r"(b1))

template<int ACT, bool BIAS, bool RES>
__global__ void __launch_bounds__(256)
mma_gemm_k(const float* __restrict__ A, const float* __restrict__ W,
           const float* __restrict__ bias, float* __restrict__ C,
           int N, int K) {
    __shared__ float As[2][BKG][BM+8];   // k-major, stride 136 -> conflict-free frag LDS
    __shared__ float Ws[2][BKG][BN+8];

    int tid = threadIdx.x;
    int wid = tid >> 5, lane = tid & 31;
    int wm = (wid >> 2) * 64;          // warp m offset (0 or 64)
    int wn = (wid & 3) * 32;           // warp n offset (0..96)
    int qr = lane >> 2;                // 0..7
    int qc = lane & 3;                 // 0..3
    int m0 = blockIdx.y * BM, n0 = blockIdx.x * BN;

    const float* Ag = A + (size_t)m0 * K;
    const float* Wg = W + (size_t)n0 * K;

    float acc[4][4][4];
#pragma unroll
    for (int i = 0; i < 4; i++)
#pragma unroll
        for (int j = 0; j < 4; j++)
#pragma unroll
            for (int c = 0; c < 4; c++) acc[i][j][c] = 0.f;

    float4 la[2], lw[2];
    // prologue load k-chunk 0
#pragma unroll
    for (int j = 0; j < 2; j++) {
        int idx = j*256 + tid; int row = idx >> 2; int kq = (idx & 3) << 2;
        la[j] = *(const float4*)(Ag + (size_t)row*K + kq);
        lw[j] = *(const float4*)(Wg + (size_t)row*K + kq);
    }
#pragma unroll
    for (int j = 0; j < 2; j++) {
        int idx = j*256 + tid; int row = idx >> 2; int kq = (idx & 3) << 2;
        As[0][kq+0][row] = la[j].x; As[0][kq+1][row] = la[j].y;
        As[0][kq+2][row] = la[j].z; As[0][kq+3][row] = la[j].w;
        Ws[0][kq+0][row] = lw[j].x; Ws[0][kq+1][row] = lw[j].y;
        Ws[0][kq+2][row] = lw[j].z; Ws[0][kq+3][row] = lw[j].w;
    }
    __syncthreads();

    int KT = K / BKG;
    for (int kt = 0; kt < KT; kt++) {
        int cur = kt & 1;
        if (kt + 1 < KT) {
#pragma unroll
            for (int j = 0; j < 2; j++) {
                int idx = j*256 + tid; int row = idx >> 2; int kq = (idx & 3) << 2;
                la[j] = *(const float4*)(Ag + (size_t)row*K + (kt+1)*BKG + kq);
                lw[j] = *(const float4*)(Wg + (size_t)row*K + (kt+1)*BKG + kq);
            }
        }
#pragma unroll
        for (int ks = 0; ks < 2; ks++) {
            int kb = ks * 8;
            uint32_t ah[4][4], al[4][4];
#pragma unroll
            for (int mt = 0; mt < 4; mt++) {
                int mb = wm + mt*16;
                float a0 = As[cur][kb+qc  ][mb+qr  ];
                float a1 = As[cur][kb+qc  ][mb+qr+8];
                float a2 = As[cur][kb+qc+4][mb+qr  ];
                float a3 = As[cur][kb+qc+4][mb+qr+8];
                split_tf32(a0, ah[mt][0], al[mt][0]);
                split_tf32(a1, ah[mt][1], al[mt][1]);
                split_tf32(a2, ah[mt][2], al[mt][2]);
                split_tf32(a3, ah[mt][3], al[mt][3]);
            }
            uint32_t bh[4][2], bl[4][2];
#pragma unroll
            for (int nt = 0; nt < 4; nt++) {
                int nb = wn + nt*8;
                float b0 = Ws[cur][kb+qc  ][nb+qr];
                float b1 = Ws[cur][kb+qc+4][nb+qr];
                split_tf32(b0, bh[nt][0], bl[nt][0]);
                split_tf32(b1, bh[nt][1], bl[nt][1]);
            }
#pragma unroll
            for (int mt = 0; mt < 4; mt++)
#pragma unroll
                for (int nt = 0; nt < 4; nt++) {
                    MMA_TF32(acc[mt][nt], ah[mt][0],ah[mt][1],ah[mt][2],ah[mt][3], bh[nt][0],bh[nt][1]);
                    MMA_TF32(acc[mt][nt], ah[mt][0],ah[mt][1],ah[mt][2],ah[mt][3], bl[nt][0],bl[nt][1]);
                    MMA_TF32(acc[mt][nt], al[mt][0],al[mt][1],al[mt][2],al[mt][3], bh[nt][0],bh[nt][1]);
                }
        }
        if (kt + 1 < KT) {
            int nxt = (kt + 1) & 1;
#pragma unroll
            for (int j = 0; j < 2; j++) {
                int idx = j*256 + tid; int row = idx >> 2; int kq = (idx & 3) << 2;
                As[nxt][kq+0][row] = la[j].x; As[nxt][kq+1][row] = la[j].y;
                As[nxt][kq+2][row] = la[j].z; As[nxt][kq+3][row] = la[j].w;
                Ws[nxt][kq+0][row] = lw[j].x; Ws[nxt][kq+1][row] = lw[j].y;
                Ws[nxt][kq+2][row] = lw[j].z; Ws[nxt][kq+3][row] = lw[j].w;
            }
        }
        __syncthreads();
    }

    // epilogue
#pragma unroll
    for (int mt = 0; mt < 4; mt++) {
#pragma unroll
        for (int nt = 0; nt < 4; nt++) {
            int n = n0 + wn + nt*8 + qc*2;
            float2 bv = make_float2(0.f, 0.f);
            if (BIAS) bv = *(const float2*)(bias + n);
#pragma unroll
            for (int half = 0; half < 2; half++) {
                int m = m0 + wm + mt*16 + qr + half*8;
                float v0 = acc[mt][nt][half*2+0] + bv.x;
                float v1 = acc[mt][nt][half*2+1] + bv.y;
                if (ACT == ACT_GELU) {
                    float x0 = v0, x1 = v1;
                    v0 = 0.5f*x0*(1.f + tanhf(0.7978845608028654f*(x0 + 0.044715f*x0*x0*x0)));
                    v1 = 0.5f*x1*(1.f + tanhf(0.7978845608028654f*(x1 + 0.044715f*x1*x1*x1)));
                }
                float* cp = C + (size_t)m*N + n;
                if (RES) { float2 r = *(const float2*)cp; v0 += r.x; v1 += r.y; }
                *(float2*)cp = make_float2(v0, v1);
            }
        }
    }
}

// ---------------- layernorm ----------------
__global__ void ln_k(const float* __restrict__ in, const float* __restrict__ g,
                     const float* __restrict__ be, float* __restrict__ out) {
    __shared__ float r1[4], r2[4];
    int m = blockIdx.x;
    const float* row = in + (size_t)m * DMODEL;
    float s = 0.f, ss = 0.f;
    for (int i = threadIdx.x; i < DMODEL; i += 128) { float v = row[i]; s += v; ss += v*v; }
#pragma unroll
    for (int off = 16; off; off >>= 1) {
        s  += __shfl_xor_sync(~0u, s, off);
        ss += __shfl_xor_sync(~0u, ss, off);
    }
    int w = threadIdx.x >> 5, lane = threadIdx.x & 31;
    if (lane == 0) { r1[w] = s; r2[w] = ss; }
    __syncthreads();
    s  = r1[0] + r1[1] + r1[2] + r1[3];
    ss = r2[0] + r2[1] + r2[2] + r2[3];
    float mean = s * (1.f/DMODEL);
    float var  = ss * (1.f/DMODEL) - mean*mean;
    float rs   = rsqrtf(var + 1e-6f);
    for (int i = threadIdx.x; i < DMODEL; i += 128)
        out[(size_t)m*DMODEL + i] = (row[i] - mean) * rs * g[i] + be[i];
}

// ---------------- dwconv + silu ----------------
__global__ void dwconv_silu_k(const float* __restrict__ cxw, const float* __restrict__ cxb,
                              const float* __restrict__ czw, const float* __restrict__ czb) {
    int idx = blockIdx.x * blockDim.x + threadIdx.x;
    if (idx >= MROWS*DMODEL) return;
    int c = idx % DMODEL;
    int m = idx / DMODEL;
    int l = m % LSEQ;
    const float* w; float acc;
    if (c < DINNER) { w = cxw + c*4;          acc = cxb[c]; }
    else            { w = czw + (c-DINNER)*4; acc = czb[c-DINNER]; }
#pragma unroll
    for (int k = 0; k < 4; k++) {
        int lp = l - 3 + k;
        if (lp >= 0) acc += w[k] * g_xz[(size_t)(m - 3 + k)*DMODEL + c];
    }
    g_xmz[idx] = acc / (1.f + __expf(-acc));
}

// ---------------- x_proj + dt_proj + softplus ----------------
__global__ void xproj_dt_k(const float* __restrict__ xpw, const float* __restrict__ dtw,
                           const float* __restrict__ dtb) {
    int m = blockIdx.x;
    __shared__ float xs[DINNER];
    __shared__ float dtr[DTRANK];
    int tid = threadIdx.x;
    xs[tid] = g_xmz[(size_t)m*DMODEL + tid];
    __syncthreads();
    int w = tid >> 5, lane = tid & 31;
    for (int j = w; j < DTRANK + 2*DSTATE; j += 8) {
        const float* wr = xpw + j*DINNER;
        float p = 0.f;
        for (int e = lane; e < DINNER; e += 32) p += xs[e] * wr[e];
#pragma unroll
        for (int off = 16; off; off >>= 1) p += __shfl_xor_sync(~0u, p, off);
        if (lane == 0) {
            if (j < DTRANK)              dtr[j] = p;
            else if (j < DTRANK+DSTATE)  g_Bm[(size_t)m*DSTATE + (j-DTRANK)] = p;
            else                         g_Cm[(size_t)m*DSTATE + (j-DTRANK-DSTATE)] = p;
        }
    }
    __syncthreads();
    float s = dtb[tid];
#pragma unroll
    for (int r = 0; r < DTRANK; r++) s += dtr[r] * dtw[tid*DTRANK + r];
    g_dt[(size_t)m*DINNER + tid] = (s > 20.f) ? s : log1pf(__expf(s));
}

// ---------------- selective scan ----------------
__global__ void scan_k(const float* __restrict__ A_log, const float* __restrict__ Dp) {
    int b = blockIdx.x;
    int d = threadIdx.x;
    __shared__ float Bs[DSTATE], Cs[DSTATE];
    float Arow[DSTATE];
#pragma unroll
    for (int n = 0; n < DSTATE; n++) Arow[n] = -__expf(A_log[d*DSTATE + n]);
    float hst[DSTATE] = {};
    float Dv = Dp[d];
    for (int l = 0; l < LSEQ; l++) {
        size_t m = (size_t)b*LSEQ + l;
        __syncthreads();
        if (d < DSTATE)        Bs[d] = g_Bm[m*DSTATE + d];
        else if (d < 2*DSTATE) Cs[d - DSTATE] = g_Cm[m*DSTATE + (d - DSTATE)];
        __syncthreads();
        float dt = g_dt[m*DINNER + d];
        float u  = g_xmz[m*DMODEL + d];
        float du = dt * u;
        float acc = 0.f;
#pragma unroll
        for (int n = 0; n < DSTATE; n++) {
            float dA = __expf(dt * Arow[n]);
            hst[n] = dA * hst[n] + du * Bs[n];
            acc += hst[n] * Cs[n];
        }
        g_ycat[m*DMODEL + d]          = acc + u * Dv;
        g_ycat[m*DMODEL + DINNER + d] = g_xmz[m*DMODEL + DINNER + d];
    }
}

// ---------------- attention ----------------
__global__ void attn_k() {
    extern __shared__ float sm[];
    float* Ks = sm;
    float* Vs = Ks + LSEQ*65;
    float* Qs = Vs + LSEQ*65;
    float* Aw = Qs + 8*64;
    int b = blockIdx.x >> 3, h = blockIdx.x & 7;
    int tid = threadIdx.x;
    const float* base = g_qkv + (size_t)b * LSEQ * (3*DMODEL);
    for (int i = tid; i < LSEQ*HDIM; i += 256) {
        int l = i / HDIM, d = i % HDIM;
        Ks[l*65 + d] = base[(size_t)l*(3*DMODEL) + DMODEL   + h*HDIM + d];
        Vs[l*65 + d] = base[(size_t)l*(3*DMODEL) + 2*DMODEL + h*HDIM + d];
    }
    __syncthreads();
    int w = tid >> 5, lane = tid & 31;
    float* qr = Qs + w*HDIM;
    float* aw = Aw + w*LSEQ;
    for (int q = w; q < LSEQ; q += 8) {
        qr[lane]      = base[(size_t)q*(3*DMODEL) + h*HDIM + lane];
        qr[lane + 32] = base[(size_t)q*(3*DMODEL) + h*HDIM + lane + 32];
        __syncwarp();
        float lmax = -1e30f;
        for (int k = lane; k < LSEQ; k += 32) {
            float s = 0.f;
            const float* kr = Ks + k*65;
#pragma unroll 16
            for (int d = 0; d < HDIM; d++) s += qr[d] * kr[d];
            s *= 0.125f;
            aw[k] = s;
            lmax = fmaxf(lmax, s);
        }
#pragma unroll
        for (int off = 16; off; off >>= 1) lmax = fmaxf(lmax, __shfl_xor_sync(~0u, lmax, off));
        float lsum = 0.f;
        for (int k = lane; k < LSEQ; k += 32) { float e = __expf(aw[k] - lmax); aw[k] = e; lsum += e; }
#pragma unroll
        for (int off = 16; off; off >>= 1) lsum += __shfl_xor_sync(~0u, lsum, off);
        float inv = 1.f / lsum;
        __syncwarp();
        float o0 = 0.f, o1 = 0.f;
        for (int k = 0; k < LSEQ; k++) {
            float a = aw[k];
            o0 += a * Vs[k*65 + lane];
            o1 += a * Vs[k*65 + lane + 32];
        }
        float* orow = g_o + ((size_t)(b*LSEQ + q))*DMODEL + h*HDIM;
        orow[lane]      = o0 * inv;
        orow[lane + 32] = o1 * inv;
        __syncwarp();
    }
}

// ---------------- mean over sequence ----------------
__global__ void meanrow_k() {
    int b = blockIdx.x, d = threadIdx.x;
    float s = 0.f;
    for (int l = 0; l < LSEQ; l++) s += g_t[((size_t)b*LSEQ + l)*DMODEL + d];
    g_tbar[b*DMODEL + d] = s * (1.f/LSEQ);
}

// ---------------- head + fc ----------------
__global__ void headfc_k(const float* __restrict__ hw, const float* __restrict__ hb,
                         const float* __restrict__ fw, const float* __restrict__ fb,
                         float* __restrict__ out) {
    int b = blockIdx.x;
    __shared__ float ts[DMODEL];
    __shared__ float ps[1024];
    int tid = threadIdx.x;
    ts[tid]       = g_tbar[b*DMODEL + tid];
    ts[tid + 256] = g_tbar[b*DMODEL + tid + 256];
    __syncthreads();
    int w = tid >> 5, lane = tid & 31;
    for (int j = w; j < 1024; j += 8) {
        const float* wr = hw + j*DMODEL;
        float p = 0.f;
        for (int e = lane; e < DMODEL; e += 32) p += ts[e] * wr[e];
#pragma unroll
        for (int off = 16; off; off >>= 1) p += __shfl_xor_sync(~0u, p, off);
        if (lane == 0) ps[j] = p + hb[j];
    }
    __syncthreads();
    if (w == 0) {
        for (int c = 0; c < 4; c++) {
            float p = 0.f;
            for (int e = lane; e < 1024; e += 32) p += ps[e] * fw[c*1024 + e];
#pragma unroll
            for (int off = 16; off; off >>= 1) p += __shfl_xor_sync(~0u, p, off);
            if (lane == 0) out[b*4 + c] = p + fb[c];
        }
    }
}

// ---------------- launch ----------------
extern "C" void kernel_launch(void* const* d_in, const int* in_sizes, int n_in,
                              void* d_out, int out_size) {
    const float* x        = (const float*)d_in[0];
    const float* patch_w  = (const float*)d_in[1];
    const float* patch_b  = (const float*)d_in[2];
    const float* ln1_g    = (const float*)d_in[3];
    const float* ln1_b    = (const float*)d_in[4];
    const float* in_proj  = (const float*)d_in[5];
    const float* convx_w  = (const float*)d_in[6];
    const float* convx_b  = (const float*)d_in[7];
    const float* convz_w  = (const float*)d_in[8];
    const float* convz_b  = (const float*)d_in[9];
    const float* x_proj_w = (const float*)d_in[10];
    const float* dt_proj_w= (const float*)d_in[11];
    const float* dt_proj_b= (const float*)d_in[12];
    const float* A_log    = (const float*)d_in[13];
    const float* Dp       = (const float*)d_in[14];
    const float* out_proj = (const float*)d_in[15];
    const float* ln2_g    = (const float*)d_in[16];
    const float* ln2_b    = (const float*)d_in[17];
    const float* qkv_w    = (const float*)d_in[18];
    const float* attn_pw  = (const float*)d_in[19];
    const float* ln3_g    = (const float*)d_in[20];
    const float* ln3_b    = (const float*)d_in[21];
    const float* mlp_w1   = (const float*)d_in[22];
    const float* mlp_b1   = (const float*)d_in[23];
    const float* mlp_w2   = (const float*)d_in[24];
    const float* mlp_b2   = (const float*)d_in[25];
    const float* head_w   = (const float*)d_in[26];
    const float* head_b   = (const float*)d_in[27];
    const float* fc_w     = (const float*)d_in[28];
    const float* fc_b     = (const float*)d_in[29];

    float *acol, *t, *h, *xz, *qkv, *o, *mid, *ycat;
    cudaGetSymbolAddress((void**)&acol, g_acol);
    cudaGetSymbolAddress((void**)&t,    g_t);
    cudaGetSymbolAddress((void**)&h,    g_h);
    cudaGetSymbolAddress((void**)&xz,   g_xz);
    cudaGetSymbolAddress((void**)&qkv,  g_qkv);
    cudaGetSymbolAddress((void**)&o,    g_o);
    cudaGetSymbolAddress((void**)&mid,  g_mid);
    cudaGetSymbolAddress((void**)&ycat, g_ycat);

    const int ATTN_SMEM = (LSEQ*65*2 + 8*64 + 8*LSEQ) * (int)sizeof(float);
    cudaFuncSetAttribute(attn_k, cudaFuncAttributeMaxDynamicSharedMemorySize, ATTN_SMEM);

    dim3 g512 (DMODEL/BN,   MROWS/BM);   // (4, 49)
    dim3 g1536(3*DMODEL/BN, MROWS/BM);   // (12, 49)
    dim3 g2048(4*DMODEL/BN, MROWS/BM);   // (16, 49)

    // 1. patch embed
    im2col_k<<<(MROWS*KPATCH + 255)/256, 256>>>(x);
    mma_gemm_k<ACT_NONE, true,  false><<<g512, 256>>>(acol, patch_w, patch_b, t, DMODEL, KPATCH);
    // 2. mamba block
    ln_k<<<MROWS, 128>>>(t, ln1_g, ln1_b, h);
    mma_gemm_k<ACT_NONE, false, false><<<g512, 256>>>(h, in_proj, nullptr, xz, DMODEL, DMODEL);
    dwconv_silu_k<<<(MROWS*DMODEL)/256, 256>>>(convx_w, convx_b, convz_w, convz_b);
    xproj_dt_k<<<MROWS, 256>>>(x_proj_w, dt_proj_w, dt_proj_b);
    scan_k<<<BATCH, 256>>>(A_log, Dp);
    mma_gemm_k<ACT_NONE, false, true ><<<g512, 256>>>(ycat, out_proj, nullptr, t, DMODEL, DMODEL);
    // 3. attention block
    ln_k<<<MROWS, 128>>>(t, ln2_g, ln2_b, h);
    mma_gemm_k<ACT_NONE, false, false><<<g1536, 256>>>(h, qkv_w, nullptr, qkv, 3*DMODEL, DMODEL);
    attn_k<<<BATCH*NHEAD, 256, ATTN_SMEM>>>();
    mma_gemm_k<ACT_NONE, false, true ><<<g512, 256>>>(o, attn_pw, nullptr, t, DMODEL, DMODEL);
    // 4. MLP block
    ln_k<<<MROWS, 128>>>(t, ln3_g, ln3_b, h);
    mma_gemm_k<ACT_GELU, true,  false><<<g2048, 256>>>(h, mlp_w1, mlp_b1, mid, 4*DMODEL, DMODEL);
    mma_gemm_k<ACT_NONE, true,  true ><<<g512, 256>>>(mid, mlp_w2, mlp_b2, t, DMODEL, 4*DMODEL);
    // 5. head
    meanrow_k<<<BATCH, DMODEL>>>();
    headfc_k<<<BATCH, 256>>>(head_w, head_b, fc_w, fc_b, (float*)d_out);
}

// round 3
// speedup vs baseline: 1.5997x; 1.4999x over previous
#include <cuda_runtime.h>
#include <cuda_bf16.h>
#include <math.h>
#include <stdint.h>

// ---------------- constants ----------------
#define BATCH 32
#define LSEQ  196
#define MROWS (BATCH*LSEQ) // 6272
#define DMODEL 512
#define DINNER 256
#define DSTATE 16
#define DTRANK 16
#define NHEAD 8
#define HDIM 64
#define KPATCH 768

// ---------------- scratch ----------------
__device__ float g_acol[MROWS*KPATCH];
__device__ float g_t   [MROWS*DMODEL];
__device__ float g_h   [MROWS*DMODEL];
__device__ float g_xz  [MROWS*DMODEL];
__device__ float g_xmz [MROWS*DMODEL];
__device__ float g_dt  [MROWS*DINNER];
__device__ float g_Bm  [MROWS*DSTATE];
__device__ float g_Cm  [MROWS*DSTATE];
__device__ float g_ycat[MROWS*DMODEL];
__device__ float g_qkv [MROWS*3*DMODEL];
__device__ float g_o   [MROWS*DMODEL];
__device__ float g_mid [MROWS*4*DMODEL];
__device__ float g_tbar[BATCH*DMODEL];

// ---------------- im2col ----------------
__global__ void im2col_k(const float* __restrict__ x) {
    int idx = blockIdx.x * blockDim.x + threadIdx.x;
    if (idx >= MROWS*KPATCH) return;
    int k = idx % KPATCH;
    int m = idx / KPATCH;
    int b = m / LSEQ, l = m % LSEQ;
    int ph = l / 14, pw = l % 14;
    int c = k / 256, rem = k % 256;
    int i = rem / 16, j = rem % 16;
    g_acol[idx] = x[(((size_t)b*3 + c)*224 + (ph*16 + i))*224 + (pw*16 + j)];
}

// ---------------- 3x-bf16 tensor-core GEMM ----------------
// C[M,N] = A[M,K] @ W[N,K]^T (+bias)(+gelu)(+residual)
// Inputs split ONCE (hi/lo bf16) at smem fill; inner loop is pure LDS+MMA.
#define ACT_NONE 0
#define ACT_GELU 1
#define BM 128
#define BN 128
#define BKG 16
#define KP 8          // k-pairs per BK chunk
#define SSTRIDE (BM+8)

__device__ __forceinline__ void split2_pack(float x, float y, uint32_t& hi, uint32_t& lo) {
    __nv_bfloat16 hx = __float2bfloat16(x);
    __nv_bfloat16 hy = __float2bfloat16(y);
    float rx = x - __bfloat162float(hx);
    float ry = y - __bfloat162float(hy);
    __nv_bfloat162 hv = __halves2bfloat162(hx, hy);       // hx in low 16
    __nv_bfloat162 lv = __floats2bfloat162_rn(rx, ry);
    hi = *(uint32_t*)&hv;
    lo = *(uint32_t*)&lv;
}

#define MMA_BF16(d, a0,a1,a2,a3, b0,b1) \
    asm volatile("mma.sync.aligned.m16n8k16.row.col.f32.bf16.bf16.f32 " \
        "{%0,%1,%2,%3},{%4,%5,%6,%7},{%8,%9},{%0,%1,%2,%3};" \
        : "+f"(d[0]),"+f"(d[1]),"+f"(d[2]),"+f"(d[3]) \
        : "r"(a0),"r"(a1),"r"(a2),"r"(a3),"r"(b0),"r"(b1))

template<int ACT, bool BIAS, bool RES>
__global__ void __launch_bounds__(256, 2)
mma_gemm_k(const float* __restrict__ A, const float* __restrict__ W,
           const float* __restrict__ bias, float* __restrict__ C,
           int N, int K) {
    __shared__ uint32_t Ah[2][KP][SSTRIDE];
    __shared__ uint32_t Al[2][KP][SSTRIDE];
    __shared__ uint32_t Wh[2][KP][SSTRIDE];
    __shared__ uint32_t Wl[2][KP][SSTRIDE];

    int tid = threadIdx.x;
    int wid = tid >> 5, lane = tid & 31;
    int wm = (wid >> 2) * 64;
    int wn = (wid & 3) * 32;
    int qr = lane >> 2;   // 0..7
    int qc = lane & 3;    // 0..3
    int m0 = blockIdx.y * BM, n0 = blockIdx.x * BN;

    const float* Ag = A + (size_t)m0 * K;
    const float* Wg = W + (size_t)n0 * K;

    float acc[4][4][4];
#pragma unroll
    for (int i = 0; i < 4; i++)
#pragma unroll
        for (int j = 0; j < 4; j++)
#pragma unroll
            for (int c = 0; c < 4; c++) acc[i][j][c] = 0.f;

    int lrow = tid >> 2;            // 0..63 (+64 for j=1)
    int lkq  = (tid & 3) << 2;      // 0,4,8,12
    int lkp  = lkq >> 1;            // k-pair base: 0,2,4,6

    float4 la[2], lw[2];
    // prologue: load + split chunk 0
#pragma unroll
    for (int j = 0; j < 2; j++) {
        int row = lrow + j*64;
        la[j] = *(const float4*)(Ag + (size_t)row*K + lkq);
        lw[j] = *(const float4*)(Wg + (size_t)row*K + lkq);
    }
#pragma unroll
    for (int j = 0; j < 2; j++) {
        int row = lrow + j*64;
        uint32_t h0,l0,h1,l1;
        split2_pack(la[j].x, la[j].y, h0, l0);
        split2_pack(la[j].z, la[j].w, h1, l1);
        Ah[0][lkp][row] = h0; Al[0][lkp][row] = l0;
        Ah[0][lkp+1][row] = h1; Al[0][lkp+1][row] = l1;
        split2_pack(lw[j].x, lw[j].y, h0, l0);
        split2_pack(lw[j].z, lw[j].w, h1, l1);
        Wh[0][lkp][row] = h0; Wl[0][lkp][row] = l0;
        Wh[0][lkp+1][row] = h1; Wl[0][lkp+1][row] = l1;
    }
    __syncthreads();

    int KT = K / BKG;
    for (int kt = 0; kt < KT; kt++) {
        int cur = kt & 1;
        if (kt + 1 < KT) {
#pragma unroll
            for (int j = 0; j < 2; j++) {
                int row = lrow + j*64;
                la[j] = *(const float4*)(Ag + (size_t)row*K + (kt+1)*BKG + lkq);
                lw[j] = *(const float4*)(Wg + (size_t)row*K + (kt+1)*BKG + lkq);
            }
        }
        // A fragments (hi+lo) for this k16
        uint32_t ah[4][4], al[4][4];
#pragma unroll
        for (int mt = 0; mt < 4; mt++) {
            int mb = wm + mt*16;
            ah[mt][0] = Ah[cur][qc  ][mb+qr];
            ah[mt][1] = Ah[cur][qc  ][mb+qr+8];
            ah[mt][2] = Ah[cur][qc+4][mb+qr];
            ah[mt][3] = Ah[cur][qc+4][mb+qr+8];
            al[mt][0] = Al[cur][qc  ][mb+qr];
            al[mt][1] = Al[cur][qc  ][mb+qr+8];
            al[mt][2] = Al[cur][qc+4][mb+qr];
            al[mt][3] = Al[cur][qc+4][mb+qr+8];
        }
#pragma unroll
        for (int nt = 0; nt < 4; nt++) {
            int nb = wn + nt*8;
            uint32_t bh0 = Wh[cur][qc  ][nb+qr];
            uint32_t bh1 = Wh[cur][qc+4][nb+qr];
            uint32_t bl0 = Wl[cur][qc  ][nb+qr];
            uint32_t bl1 = Wl[cur][qc+4][nb+qr];
#pragma unroll
            for (int mt = 0; mt < 4; mt++) {
                MMA_BF16(acc[mt][nt], ah[mt][0],ah[mt][1],ah[mt][2],ah[mt][3], bh0,bh1);
                MMA_BF16(acc[mt][nt], ah[mt][0],ah[mt][1],ah[mt][2],ah[mt][3], bl0,bl1);
                MMA_BF16(acc[mt][nt], al[mt][0],al[mt][1],al[mt][2],al[mt][3], bh0,bh1);
            }
        }
        if (kt + 1 < KT) {
            int nxt = (kt + 1) & 1;
#pragma unroll
            for (int j = 0; j < 2; j++) {
                int row = lrow + j*64;
                uint32_t h0,l0,h1,l1;
                split2_pack(la[j].x, la[j].y, h0, l0);
                split2_pack(la[j].z, la[j].w, h1, l1);
                Ah[nxt][lkp][row] = h0; Al[nxt][lkp][row] = l0;
                Ah[nxt][lkp+1][row] = h1; Al[nxt][lkp+1][row] = l1;
                split2_pack(lw[j].x, lw[j].y, h0, l0);
                split2_pack(lw[j].z, lw[j].w, h1, l1);
                Wh[nxt][lkp][row] = h0; Wl[nxt][lkp][row] = l0;
                Wh[nxt][lkp+1][row] = h1; Wl[nxt][lkp+1][row] = l1;
            }
        }
        __syncthreads();
    }

    // epilogue
#pragma unroll
    for (int mt = 0; mt < 4; mt++) {
#pragma unroll
        for (int nt = 0; nt < 4; nt++) {
            int n = n0 + wn + nt*8 + qc*2;
            float2 bv = make_float2(0.f, 0.f);
            if (BIAS) bv = *(const float2*)(bias + n);
#pragma unroll
            for (int half = 0; half < 2; half++) {
                int m = m0 + wm + mt*16 + qr + half*8;
                float v0 = acc[mt][nt][half*2+0] + bv.x;
                float v1 = acc[mt][nt][half*2+1] + bv.y;
                if (ACT == ACT_GELU) {
                    float x0 = v0, x1 = v1;
                    v0 = 0.5f*x0*(1.f + tanhf(0.7978845608028654f*(x0 + 0.044715f*x0*x0*x0)));
                    v1 = 0.5f*x1*(1.f + tanhf(0.7978845608028654f*(x1 + 0.044715f*x1*x1*x1)));
                }
                float* cp = C + (size_t)m*N + n;
                if (RES) { float2 r = *(const float2*)cp; v0 += r.x; v1 += r.y; }
                *(float2*)cp = make_float2(v0, v1);
            }
        }
    }
}

// ---------------- layernorm ----------------
__global__ void ln_k(const float* __restrict__ in, const float* __restrict__ g,
                     const float* __restrict__ be, float* __restrict__ out) {
    __shared__ float r1[4], r2[4];
    int m = blockIdx.x;
    const float* row = in + (size_t)m * DMODEL;
    float s = 0.f, ss = 0.f;
    for (int i = threadIdx.x; i < DMODEL; i += 128) { float v = row[i]; s += v; ss += v*v; }
#pragma unroll
    for (int off = 16; off; off >>= 1) {
        s  += __shfl_xor_sync(~0u, s, off);
        ss += __shfl_xor_sync(~0u, ss, off);
    }
    int w = threadIdx.x >> 5, lane = threadIdx.x & 31;
    if (lane == 0) { r1[w] = s; r2[w] = ss; }
    __syncthreads();
    s  = r1[0] + r1[1] + r1[2] + r1[3];
    ss = r2[0] + r2[1] + r2[2] + r2[3];
    float mean = s * (1.f/DMODEL);
    float var  = ss * (1.f/DMODEL) - mean*mean;
    float rs   = rsqrtf(var + 1e-6f);
    for (int i = threadIdx.x; i < DMODEL; i += 128)
        out[(size_t)m*DMODEL + i] = (row[i] - mean) * rs * g[i] + be[i];
}

// ---------------- dwconv + silu ----------------
__global__ void dwconv_silu_k(const float* __restrict__ cxw, const float* __restrict__ cxb,
                              const float* __restrict__ czw, const float* __restrict__ czb) {
    int idx = blockIdx.x * blockDim.x + threadIdx.x;
    if (idx >= MROWS*DMODEL) return;
    int c = idx % DMODEL;
    int m = idx / DMODEL;
    int l = m % LSEQ;
    const float* w; float acc;
    if (c < DINNER) { w = cxw + c*4;          acc = cxb[c]; }
    else            { w = czw + (c-DINNER)*4; acc = czb[c-DINNER]; }
#pragma unroll
    for (int k = 0; k < 4; k++) {
        int lp = l - 3 + k;
        if (lp >= 0) acc += w[k] * g_xz[(size_t)(m - 3 + k)*DMODEL + c];
    }
    g_xmz[idx] = acc / (1.f + __expf(-acc));
}

// ---------------- x_proj + dt_proj + softplus ----------------
__global__ void xproj_dt_k(const float* __restrict__ xpw, const float* __restrict__ dtw,
                           const float* __restrict__ dtb) {
    int m = blockIdx.x;
    __shared__ float xs[DINNER];
    __shared__ float dtr[DTRANK];
    int tid = threadIdx.x;
    xs[tid] = g_xmz[(size_t)m*DMODEL + tid];
    __syncthreads();
    int w = tid >> 5, lane = tid & 31;
    for (int j = w; j < DTRANK + 2*DSTATE; j += 8) {
        const float* wr = xpw + j*DINNER;
        float p = 0.f;
        for (int e = lane; e < DINNER; e += 32) p += xs[e] * wr[e];
#pragma unroll
        for (int off = 16; off; off >>= 1) p += __shfl_xor_sync(~0u, p, off);
        if (lane == 0) {
            if (j < DTRANK)              dtr[j] = p;
            else if (j < DTRANK+DSTATE)  g_Bm[(size_t)m*DSTATE + (j-DTRANK)] = p;
            else                         g_Cm[(size_t)m*DSTATE + (j-DTRANK-DSTATE)] = p;
        }
    }
    __syncthreads();
    float s = dtb[tid];
#pragma unroll
    for (int r = 0; r < DTRANK; r++) s += dtr[r] * dtw[tid*DTRANK + r];
    g_dt[(size_t)m*DINNER + tid] = (s > 20.f) ? s : log1pf(__expf(s));
}

// ---------------- selective scan ----------------
__global__ void scan_k(const float* __restrict__ A_log, const float* __restrict__ Dp) {
    int b = blockIdx.x;
    int d = threadIdx.x;
    __shared__ float Bs[DSTATE], Cs[DSTATE];
    float Arow[DSTATE];
#pragma unroll
    for (int n = 0; n < DSTATE; n++) Arow[n] = -__expf(A_log[d*DSTATE + n]);
    float hst[DSTATE] = {};
    float Dv = Dp[d];
    for (int l = 0; l < LSEQ; l++) {
        size_t m = (size_t)b*LSEQ + l;
        __syncthreads();
        if (d < DSTATE)        Bs[d] = g_Bm[m*DSTATE + d];
        else if (d < 2*DSTATE) Cs[d - DSTATE] = g_Cm[m*DSTATE + (d - DSTATE)];
        __syncthreads();
        float dt = g_dt[m*DINNER + d];
        float u  = g_xmz[m*DMODEL + d];
        float du = dt * u;
        float acc = 0.f;
#pragma unroll
        for (int n = 0; n < DSTATE; n++) {
            float dA = __expf(dt * Arow[n]);
            hst[n] = dA * hst[n] + du * Bs[n];
            acc += hst[n] * Cs[n];
        }
        g_ycat[m*DMODEL + d]          = acc + u * Dv;
        g_ycat[m*DMODEL + DINNER + d] = g_xmz[m*DMODEL + DINNER + d];
    }
}

// ---------------- attention ----------------
__global__ void attn_k() {
    extern __shared__ float sm[];
    float* Ks = sm;
    float* Vs = Ks + LSEQ*65;
    float* Qs = Vs + LSEQ*65;
    float* Aw = Qs + 8*64;
    int b = blockIdx.x >> 3, h = blockIdx.x & 7;
    int tid = threadIdx.x;
    const float* base = g_qkv + (size_t)b * LSEQ * (3*DMODEL);
    for (int i = tid; i < LSEQ*HDIM; i += 256) {
        int l = i / HDIM, d = i % HDIM;
        Ks[l*65 + d] = base[(size_t)l*(3*DMODEL) + DMODEL   + h*HDIM + d];
        Vs[l*65 + d] = base[(size_t)l*(3*DMODEL) + 2*DMODEL + h*HDIM + d];
    }
    __syncthreads();
    int w = tid >> 5, lane = tid & 31;
    float* qr = Qs + w*HDIM;
    float* aw = Aw + w*LSEQ;
    for (int q = w; q < LSEQ; q += 8) {
        qr[lane]      = base[(size_t)q*(3*DMODEL) + h*HDIM + lane];
        qr[lane + 32] = base[(size_t)q*(3*DMODEL) + h*HDIM + lane + 32];
        __syncwarp();
        float lmax = -1e30f;
        for (int k = lane; k < LSEQ; k += 32) {
            float s = 0.f;
            const float* kr = Ks + k*65;
#pragma unroll 16
            for (int d = 0; d < HDIM; d++) s += qr[d] * kr[d];
            s *= 0.125f;
            aw[k] = s;
            lmax = fmaxf(lmax, s);
        }
#pragma unroll
        for (int off = 16; off; off >>= 1) lmax = fmaxf(lmax, __shfl_xor_sync(~0u, lmax, off));
        float lsum = 0.f;
        for (int k = lane; k < LSEQ; k += 32) { float e = __expf(aw[k] - lmax); aw[k] = e; lsum += e; }
#pragma unroll
        for (int off = 16; off; off >>= 1) lsum += __shfl_xor_sync(~0u, lsum, off);
        float inv = 1.f / lsum;
        __syncwarp();
        float o0 = 0.f, o1 = 0.f;
        for (int k = 0; k < LSEQ; k++) {
            float a = aw[k];
            o0 += a * Vs[k*65 + lane];
            o1 += a * Vs[k*65 + lane + 32];
        }
        float* orow = g_o + ((size_t)(b*LSEQ + q))*DMODEL + h*HDIM;
        orow[lane]      = o0 * inv;
        orow[lane + 32] = o1 * inv;
        __syncwarp();
    }
}

// ---------------- mean over sequence ----------------
__global__ void meanrow_k() {
    int b = blockIdx.x, d = threadIdx.x;
    float s = 0.f;
    for (int l = 0; l < LSEQ; l++) s += g_t[((size_t)b*LSEQ + l)*DMODEL + d];
    g_tbar[b*DMODEL + d] = s * (1.f/LSEQ);
}

// ---------------- head + fc ----------------
__global__ void headfc_k(const float* __restrict__ hw, const float* __restrict__ hb,
                         const float* __restrict__ fw, const float* __restrict__ fb,
                         float* __restrict__ out) {
    int b = blockIdx.x;
    __shared__ float ts[DMODEL];
    __shared__ float ps[1024];
    int tid = threadIdx.x;
    ts[tid]       = g_tbar[b*DMODEL + tid];
    ts[tid + 256] = g_tbar[b*DMODEL + tid + 256];
    __syncthreads();
    int w = tid >> 5, lane = tid & 31;
    for (int j = w; j < 1024; j += 8) {
        const float* wr = hw + j*DMODEL;
        float p = 0.f;
        for (int e = lane; e < DMODEL; e += 32) p += ts[e] * wr[e];
#pragma unroll
        for (int off = 16; off; off >>= 1) p += __shfl_xor_sync(~0u, p, off);
        if (lane == 0) ps[j] = p + hb[j];
    }
    __syncthreads();
    if (w == 0) {
        for (int c = 0; c < 4; c++) {
            float p = 0.f;
            for (int e = lane; e < 1024; e += 32) p += ps[e] * fw[c*1024 + e];
#pragma unroll
            for (int off = 16; off; off >>= 1) p += __shfl_xor_sync(~0u, p, off);
            if (lane == 0) out[b*4 + c] = p + fb[c];
        }
    }
}

// ---------------- launch ----------------
extern "C" void kernel_launch(void* const* d_in, const int* in_sizes, int n_in,
                              void* d_out, int out_size) {
    const float* x        = (const float*)d_in[0];
    const float* patch_w  = (const float*)d_in[1];
    const float* patch_b  = (const float*)d_in[2];
    const float* ln1_g    = (const float*)d_in[3];
    const float* ln1_b    = (const float*)d_in[4];
    const float* in_proj  = (const float*)d_in[5];
    const float* convx_w  = (const float*)d_in[6];
    const float* convx_b  = (const float*)d_in[7];
    const float* convz_w  = (const float*)d_in[8];
    const float* convz_b  = (const float*)d_in[9];
    const float* x_proj_w = (const float*)d_in[10];
    const float* dt_proj_w= (const float*)d_in[11];
    const float* dt_proj_b= (const float*)d_in[12];
    const float* A_log    = (const float*)d_in[13];
    const float* Dp       = (const float*)d_in[14];
    const float* out_proj = (const float*)d_in[15];
    const float* ln2_g    = (const float*)d_in[16];
    const float* ln2_b    = (const float*)d_in[17];
    const float* qkv_w    = (const float*)d_in[18];
    const float* attn_pw  = (const float*)d_in[19];
    const float* ln3_g    = (const float*)d_in[20];
    const float* ln3_b    = (const float*)d_in[21];
    const float* mlp_w1   = (const float*)d_in[22];
    const float* mlp_b1   = (const float*)d_in[23];
    const float* mlp_w2   = (const float*)d_in[24];
    const float* mlp_b2   = (const float*)d_in[25];
    const float* head_w   = (const float*)d_in[26];
    const float* head_b   = (const float*)d_in[27];
    const float* fc_w     = (const float*)d_in[28];
    const float* fc_b     = (const float*)d_in[29];

    float *acol, *t, *h, *xz, *qkv, *o, *mid, *ycat;
    cudaGetSymbolAddress((void**)&acol, g_acol);
    cudaGetSymbolAddress((void**)&t,    g_t);
    cudaGetSymbolAddress((void**)&h,    g_h);
    cudaGetSymbolAddress((void**)&xz,   g_xz);
    cudaGetSymbolAddress((void**)&qkv,  g_qkv);
    cudaGetSymbolAddress((void**)&o,    g_o);
    cudaGetSymbolAddress((void**)&mid,  g_mid);
    cudaGetSymbolAddress((void**)&ycat, g_ycat);

    const int ATTN_SMEM = (LSEQ*65*2 + 8*64 + 8*LSEQ) * (int)sizeof(float);
    cudaFuncSetAttribute(attn_k, cudaFuncAttributeMaxDynamicSharedMemorySize, ATTN_SMEM);

    dim3 g512 (DMODEL/BN,   MROWS/BM);   // (4, 49)
    dim3 g1536(3*DMODEL/BN, MROWS/BM);   // (12, 49)
    dim3 g2048(4*DMODEL/BN, MROWS/BM);   // (16, 49)

    // 1. patch embed
    im2col_k<<<(MROWS*KPATCH + 255)/256, 256>>>(x);
    mma_gemm_k<ACT_NONE, true,  false><<<g512, 256>>>(acol, patch_w, patch_b, t, DMODEL, KPATCH);
    // 2. mamba block
    ln_k<<<MROWS, 128>>>(t, ln1_g, ln1_b, h);
    mma_gemm_k<ACT_NONE, false, false><<<g512, 256>>>(h, in_proj, nullptr, xz, DMODEL, DMODEL);
    dwconv_silu_k<<<(MROWS*DMODEL)/256, 256>>>(convx_w, convx_b, convz_w, convz_b);
    xproj_dt_k<<<MROWS, 256>>>(x_proj_w, dt_proj_w, dt_proj_b);
    scan_k<<<BATCH, 256>>>(A_log, Dp);
    mma_gemm_k<ACT_NONE, false, true ><<<g512, 256>>>(ycat, out_proj, nullptr, t, DMODEL, DMODEL);
    // 3. attention block
    ln_k<<<MROWS, 128>>>(t, ln2_g, ln2_b, h);
    mma_gemm_k<ACT_NONE, false, false><<<g1536, 256>>>(h, qkv_w, nullptr, qkv, 3*DMODEL, DMODEL);
    attn_k<<<BATCH*NHEAD, 256, ATTN_SMEM>>>();
    mma_gemm_k<ACT_NONE, false, true ><<<g512, 256>>>(o, attn_pw, nullptr, t, DMODEL, DMODEL);
    // 4. MLP block
    ln_k<<<MROWS, 128>>>(t, ln3_g, ln3_b, h);
    mma_gemm_k<ACT_GELU, true,  false><<<g2048, 256>>>(h, mlp_w1, mlp_b1, mid, 4*DMODEL, DMODEL);
    mma_gemm_k<ACT_NONE, true,  true ><<<g512, 256>>>(mid, mlp_w2, mlp_b2, t, DMODEL, 4*DMODEL);
    // 5. head
    meanrow_k<<<BATCH, DMODEL>>>();
    headfc_k<<<BATCH, 256>>>(head_w, head_b, fc_w, fc_b, (float*)d_out);
}